// round 9
// baseline (speedup 1.0000x reference)
#include <cuda_runtime.h>
#include <cstdint>

// VINeuralODE: B=128, D=32, H=128, 8 Dopri5 steps x 6 field evals.
// dlogpdt = -tr(W3 D2 W2 D1 W1) = -sum_u d1_u (M[u,:]·d2), M precomputed.
// Warp-specialized: warps 0-3 compute h1/h2 (one H-row per thread, weights in
// regs, packed fma.rn.f32x2); warp 4 does W3 quarter + dxdt assembly + dopri5
// update; warps 5-7 do W3 quarters + M-row trace dots.
// h2/d2 (and d1) double-buffered -> no "consumed" barrier on the compute path.

#define Dd 32
#define Hh 128
#define NSTEPS 8
#define NST 48

__device__ __align__(16) float d_M[Hh * Hh];

__constant__ float c_C[6]  = {0.0f, 0.2f, 0.3f, 0.8f, 0.88888888888888888f, 1.0f};
__constant__ float c_BW[6] = {35.0f/384.0f, 0.0f, 500.0f/1113.0f, 125.0f/192.0f,
                              -2187.0f/6784.0f, 11.0f/84.0f};

#define BAR_SYNC(id, cnt)   asm volatile("bar.sync %0, %1;"   :: "r"(id), "r"(cnt) : "memory")
#define BAR_ARRIVE(id, cnt) asm volatile("bar.arrive %0, %1;" :: "r"(id), "r"(cnt) : "memory")

__global__ void precompute_M_kernel(const float* __restrict__ W1,
                                    const float* __restrict__ W2,
                                    const float* __restrict__ W3) {
    int jj = blockIdx.x;
    int kk = threadIdx.x;
    float a = 0.f;
#pragma unroll
    for (int i = 0; i < Dd; ++i)
        a += W1[kk * Dd + i] * W3[i * Hh + jj];
    d_M[kk * Hh + jj] = a * W2[jj * Hh + kk];
}

__device__ __forceinline__ float ftanh(float x) {
    float e = __expf(2.0f * x);
    return 1.0f - __fdividef(2.0f, e + 1.0f);
}

__device__ __forceinline__ uint64_t ffma2(uint64_t a, uint64_t b, uint64_t c) {
    uint64_t d;
    asm("fma.rn.f32x2 %0, %1, %2, %3;" : "=l"(d) : "l"(a), "l"(b), "l"(c));
    return d;
}
__device__ __forceinline__ uint64_t pk2(float x, float y) {
    uint64_t r; asm("mov.b64 %0, {%1, %2};" : "=l"(r) : "f"(x), "f"(y)); return r;
}
__device__ __forceinline__ float hsum2(uint64_t v) {
    float a, b; asm("mov.b64 {%0, %1}, %2;" : "=f"(a), "=f"(b) : "l"(v)); return a + b;
}
__device__ __forceinline__ uint32_t sptr(const void* p) {
    return (uint32_t)__cvta_generic_to_shared(p);
}

// 128-length dot, 8 accumulator chains (dep depth 8 FFMA2).
__device__ __forceinline__ float dot128(const uint64_t* __restrict__ w, uint32_t saddr) {
    uint64_t a0=0,a1=0,a2=0,a3=0,a4=0,a5=0,a6=0,a7=0;
#pragma unroll
    for (int i = 0; i < 32; i += 4) {
        uint64_t p0,p1,p2,p3,p4,p5,p6,p7;
        asm volatile("ld.shared.v2.u64 {%0, %1}, [%2];" : "=l"(p0), "=l"(p1) : "r"(saddr + 16u*i));
        asm volatile("ld.shared.v2.u64 {%0, %1}, [%2];" : "=l"(p2), "=l"(p3) : "r"(saddr + 16u*i + 16u));
        asm volatile("ld.shared.v2.u64 {%0, %1}, [%2];" : "=l"(p4), "=l"(p5) : "r"(saddr + 16u*i + 32u));
        asm volatile("ld.shared.v2.u64 {%0, %1}, [%2];" : "=l"(p6), "=l"(p7) : "r"(saddr + 16u*i + 48u));
        a0 = ffma2(w[2*i],   p0, a0);
        a1 = ffma2(w[2*i+1], p1, a1);
        a2 = ffma2(w[2*i+2], p2, a2);
        a3 = ffma2(w[2*i+3], p3, a3);
        a4 = ffma2(w[2*i+4], p4, a4);
        a5 = ffma2(w[2*i+5], p5, a5);
        a6 = ffma2(w[2*i+6], p6, a6);
        a7 = ffma2(w[2*i+7], p7, a7);
    }
    return ((hsum2(a0)+hsum2(a1)) + (hsum2(a2)+hsum2(a3)))
         + ((hsum2(a4)+hsum2(a5)) + (hsum2(a6)+hsum2(a7)));
}

// 32-length dot, 4 accumulator chains.
__device__ __forceinline__ float dot32(const uint64_t* __restrict__ w, uint32_t saddr) {
    uint64_t a0=0,a1=0,a2=0,a3=0;
#pragma unroll
    for (int i = 0; i < 8; i += 2) {
        uint64_t p0,p1,p2,p3;
        asm volatile("ld.shared.v2.u64 {%0, %1}, [%2];" : "=l"(p0), "=l"(p1) : "r"(saddr + 16u*i));
        asm volatile("ld.shared.v2.u64 {%0, %1}, [%2];" : "=l"(p2), "=l"(p3) : "r"(saddr + 16u*i + 16u));
        a0 = ffma2(w[2*i],   p0, a0);
        a1 = ffma2(w[2*i+1], p1, a1);
        a2 = ffma2(w[2*i+2], p2, a2);
        a3 = ffma2(w[2*i+3], p3, a3);
    }
    return (hsum2(a0)+hsum2(a1)) + (hsum2(a2)+hsum2(a3));
}

__global__ __launch_bounds__(256, 1)
void ode_kernel(const float* __restrict__ x0,
                const float* __restrict__ W1,
                const float* __restrict__ u1,
                const float* __restrict__ b1,
                const float* __restrict__ W2,
                const float* __restrict__ b2,
                const float* __restrict__ W3,
                const float* __restrict__ b3,
                const float* __restrict__ prec,
                float* __restrict__ out, int B) {
    const int s    = blockIdx.x;
    const int tid  = threadIdx.x;
    const int lane = tid & 31;
    const int warp = tid >> 5;
    const float dt = 1.0f / NSTEPS;
    const float HALF_LOG2PI = 0.9189385332046727f;

    __shared__ __align__(16) float sh_xs[Dd];
    __shared__ __align__(16) float sh_h1[Hh];
    __shared__ __align__(16) float sh_d1[2][Hh];
    __shared__ __align__(16) float sh_h2[2][Hh];
    __shared__ __align__(16) float sh_d2[2][Hh];
    __shared__ float sh_dxp[Hh];          // W3 quarter partials (warps 5-7 -> idx 32..127)
    __shared__ float sh_tw[NST][4];
    __shared__ float sh_xh[NST + 1][Dd];
    __shared__ float sh_kd[NST][Dd];
    __shared__ float b1s[Hh], u1s[Hh], b2s[Hh], b3s[Dd], precs[Dd];
    __shared__ float sh_pld[8], sh_pkl[8], sh_lp;

    const uint32_t a_xs = sptr(sh_xs);
    const uint32_t a_h1 = sptr(sh_h1);
    const uint32_t a_h2 = sptr(sh_h2[0]);
    const uint32_t a_d2 = sptr(sh_d2[0]);

    if (tid < Hh) { b1s[tid] = b1[tid]; u1s[tid] = u1[tid]; b2s[tid] = b2[tid]; }
    if (tid < Dd) {
        b3s[tid] = b3[tid]; precs[tid] = prec[tid];
        float xv = x0[s * Dd + tid];
        sh_xs[tid] = xv;
        sh_xh[0][tid] = xv;
    }
    __syncthreads();

    if (warp < 4) {
        // ================= COMPUTE (threads 0-127), H-row j = tid ============
        const int j = tid;
        uint64_t w1p[16];   // W1[j,0:32] packed
        uint64_t w2p[64];   // W2[j,0:128] packed
        {
            const float4* p = (const float4*)(W1 + j * Dd);
#pragma unroll
            for (int i = 0; i < 8; ++i) {
                float4 v = p[i];
                w1p[2*i] = pk2(v.x, v.y); w1p[2*i+1] = pk2(v.z, v.w);
            }
        }
        {
            const float4* p = (const float4*)(W2 + j * Hh);
#pragma unroll
            for (int i = 0; i < 32; ++i) {
                float4 v = p[i];
                w2p[2*i] = pk2(v.x, v.y); w2p[2*i+1] = pk2(v.z, v.w);
            }
        }
        const float b1j = b1s[j], u1j = u1s[j], b2j = b2s[j];

#pragma unroll 1
        for (int gst = 0; gst < NST; ++gst) {
            const int st = gst % 6;
            const int stp = gst / 6;
            const int buf = gst & 1;
            float ts = ((float)stp + c_C[st]) * dt;

            BAR_SYNC(5, 160);                         // xs ready (warp4 / prime)
            // ---- h1 ----
            float a = dot32(w1p, a_xs) + b1j + ts * u1j;
            float h1 = ftanh(a);
            sh_h1[j] = h1;
            sh_d1[buf][j] = 1.f - h1 * h1;
            BAR_SYNC(1, 128);                         // all h1 written
            // ---- h2 (write into double buffer; no consumption wait) ----
            float b = dot128(w2p, a_h1) + b2j;
            float h2 = ftanh(b);
            sh_h2[buf][j] = h2;
            sh_d2[buf][j] = 1.f - h2 * h2;
            BAR_ARRIVE(2, 256);                       // h2/d2[buf] ready
        }
    } else {
        // ================= TRACE (threads 128-255) ===========================
        const int u  = tid - 128;        // 0..127
        const int tw = warp - 4;         // 0..3 (W3 column quarter)
        const int rw = u & 31;           // W3 output row
        uint64_t wmp[64];   // M[u,0:128] packed
        uint64_t w3p[16];   // W3[rw, tw*32 : +32] packed
        {
            const float4* p = (const float4*)(d_M + u * Hh);
#pragma unroll
            for (int i = 0; i < 32; ++i) {
                float4 v = p[i];
                wmp[2*i] = pk2(v.x, v.y); wmp[2*i+1] = pk2(v.z, v.w);
            }
        }
        {
            const float4* p = (const float4*)(W3 + rw * Hh + tw * 32);
#pragma unroll
            for (int i = 0; i < 8; ++i) {
                float4 v = p[i];
                w3p[2*i] = pk2(v.x, v.y); w3p[2*i+1] = pk2(v.z, v.w);
            }
        }
        float yv = 0.f, k0 = 0.f, k1 = 0.f, k2 = 0.f, k3 = 0.f, k4 = 0.f;
        if (tw == 0) {
            yv = x0[s * Dd + lane];
            BAR_ARRIVE(5, 160);                       // prime "xs ready" (xs = x0)
        }

#pragma unroll 1
        for (int gst = 0; gst < NST; ++gst) {
            const int st = gst % 6;
            const int buf = gst & 1;
            BAR_SYNC(2, 256);                         // h2/d2[buf] ready

            // ---- W3 quarter dot: row rw, cols tw*32..+31 ----
            float qd = dot32(w3p, a_h2 + 512u * buf + 4u * (tw * 32));

            if (tw == 0) {
                // warp 4: gather partials, dxdt, dopri5 update
                BAR_SYNC(4, 128);                     // warps 5-7 partials ready
                float dxv = qd + ((sh_dxp[32 + lane] + sh_dxp[64 + lane])
                                + sh_dxp[96 + lane]) + b3s[lane];
                sh_kd[gst][lane] = dxv;
                float acc;
                switch (st) {
                    case 0: k0 = dxv; acc = 0.2f * k0; break;
                    case 1: k1 = dxv; acc = (3.f/40.f) * k0 + (9.f/40.f) * k1; break;
                    case 2: k2 = dxv; acc = (44.f/45.f) * k0 + (-56.f/15.f) * k1 + (32.f/9.f) * k2; break;
                    case 3: k3 = dxv; acc = (19372.f/6561.f) * k0 + (-25360.f/2187.f) * k1
                                          + (64448.f/6561.f) * k2 + (-212.f/729.f) * k3; break;
                    case 4: k4 = dxv; acc = (9017.f/3168.f) * k0 + (-355.f/33.f) * k1
                                          + (46732.f/5247.f) * k2 + (49.f/176.f) * k3
                                          + (-5103.f/18656.f) * k4; break;
                    default:
                        yv = yv + dt * ( (35.f/384.f)     * k0
                                       + (500.f/1113.f)   * k2
                                       + (125.f/192.f)    * k3
                                       + (-2187.f/6784.f) * k4
                                       + (11.f/84.f)      * dxv );
                        acc = 0.f; break;
                }
                float xnew = (st < 5) ? (yv + dt * acc) : yv;
                sh_xs[lane] = xnew;
                sh_xh[gst + 1][lane] = xnew;
                BAR_ARRIVE(5, 160);                   // xs ready
            } else {
                sh_dxp[u] = qd;
                BAR_ARRIVE(4, 128);                   // partial ready for warp 4
            }

            // ---- M-row trace dot (off critical path) ----
            float val = sh_d1[buf][u] * dot128(wmp, a_d2 + 512u * buf);

#pragma unroll
            for (int off = 16; off > 0; off >>= 1)
                val += __shfl_xor_sync(0xffffffffu, val, off);
            if (lane == 0) sh_tw[gst][tw] = val;
        }
        if (tw == 0) out[s * Dd + lane] = yv;         // final z
    }
    __syncthreads();

    // ================= FINAL EPILOGUE: 48 stage reductions over 8 warps ======
    {
        float acc_ld = 0.f, acc_kl = 0.f;
#pragma unroll 1
        for (int i = 0; i < 6; ++i) {
            int g = warp + 8 * i;
            int st = g % 6;
            int stp = g / 6;
            float ts = ((float)stp + c_C[st]) * dt;
            float dlogp = -((sh_tw[g][0] + sh_tw[g][1]) + (sh_tw[g][2] + sh_tw[g][3]));
            float omt = 1.f - ts;
            float cA = -0.5f * omt * omt;
            float cB = -0.5f * omt * (1.f + ts);
            float xv  = sh_xh[g][lane];
            float dxv = sh_kd[g][lane];
            float qv = (cA * (-0.5f * xv * xv - HALF_LOG2PI) + cB * (-precs[lane] * xv)) * dxv;
#pragma unroll
            for (int off = 16; off > 0; off >>= 1)
                qv += __shfl_xor_sync(0xffffffffu, qv, off);
            float bw = c_BW[st];
            acc_ld += bw * dlogp;
            acc_kl += bw * (qv + omt * dlogp);
        }
        if (lane == 0) { sh_pld[warp] = acc_ld; sh_pkl[warp] = acc_kl; }
        if (warp == 1) {
            float xv = x0[s * Dd + lane];
            float lp = -0.5f * xv * xv - HALF_LOG2PI;
#pragma unroll
            for (int off = 16; off > 0; off >>= 1)
                lp += __shfl_xor_sync(0xffffffffu, lp, off);
            if (lane == 0) sh_lp = lp;
        }
    }
    __syncthreads();
    if (tid == 0) {
        float ld = 0.f, kl = 0.f;
#pragma unroll
        for (int w = 0; w < 8; ++w) { ld += sh_pld[w]; kl += sh_pkl[w]; }
        out[B * Dd + s]     = sh_lp + dt * ld;
        out[B * Dd + B + s] = dt * kl;
    }
}

extern "C" void kernel_launch(void* const* d_in, const int* in_sizes, int n_in,
                              void* d_out, int out_size) {
    const float* x0   = (const float*)d_in[0];
    const float* W1   = (const float*)d_in[1];
    const float* u1   = (const float*)d_in[2];
    const float* b1   = (const float*)d_in[3];
    const float* W2   = (const float*)d_in[4];
    const float* b2   = (const float*)d_in[5];
    const float* W3   = (const float*)d_in[6];
    const float* b3   = (const float*)d_in[7];
    const float* prec = (const float*)d_in[8];
    float* out = (float*)d_out;
    const int B = in_sizes[0] / Dd;

    precompute_M_kernel<<<Hh, Hh>>>(W1, W2, W3);
    ode_kernel<<<B, 256>>>(x0, W1, u1, b1, W2, b2, W3, b3, prec, out, B);
}